// round 12
// baseline (speedup 1.0000x reference)
#include <cuda_runtime.h>

#define NC 256
#define NCG (NC / 2)        // 128 float2 channel-groups
#define FH 38
#define FW 38
#define NHW (FH * FW)       // 1444
#define PPH 7
#define PPW 7
#define NBINS (PPH * PPW)   // 49
#define OUT_PER_ROI (NC * NBINS)  // 12544

// Transposed features: [H][W][C], channel-contiguous for coalesced warp reads.
__device__ float g_ft[NHW * NC];

__global__ void transpose_kernel(const float* __restrict__ f) {
    __shared__ float t[32][33];
    const int hw0 = blockIdx.x * 32;
    const int c0  = blockIdx.y * 32;

    int hw = hw0 + threadIdx.x;
    int c  = c0 + threadIdx.y;
    if (hw < NHW) t[threadIdx.y][threadIdx.x] = f[c * NHW + hw];
    __syncthreads();

    int hw2 = hw0 + threadIdx.y;
    int c2  = c0 + threadIdx.x;
    if (hw2 < NHW) g_ft[hw2 * NC + c2] = t[threadIdx.x][threadIdx.y];
}

// One block per (roi, ph). Thread = 2 channels (float2).
// All 7 pw-bins of a ph-row share the same h range -> per h, issue one
// column load for EACH bin (7 independent LDGs = MLP 7), clamped within
// each bin so the j-loop runs to max bin width. No membership predicates.
__global__ void pool_kernel(const float* __restrict__ rois,
                            const float* __restrict__ sscale,
                            float* __restrict__ out) {
    __shared__ float s_out[NC * PPW];   // 7168 B

    const int roi = blockIdx.x;
    const int ph  = blockIdx.y;
    const int cg  = threadIdx.x;        // channels 2cg, 2cg+1
    const float scale = *sscale;

    const float* r = rois + roi * 5;
    // jnp.round = half-to-even = rintf
    const int x1 = (int)rintf(__fmul_rn(r[1], scale));
    const int y1 = (int)rintf(__fmul_rn(r[2], scale));
    const int x2 = (int)rintf(__fmul_rn(r[3], scale));
    const int y2 = (int)rintf(__fmul_rn(r[4], scale));

    // Match XLA: w/7 lowered to w * RN(1/7)
    const float RCP7 = 1.0f / 7.0f;
    const float bw = __fmul_rn((float)max(x2 - x1 + 1, 1), RCP7);
    const float bh = __fmul_rn((float)max(y2 - y1 + 1, 1), RCP7);

    int hs = (int)floorf(__fmul_rn((float)ph, bh));
    int he = (int)ceilf(__fmul_rn((float)(ph + 1), bh));
    hs = min(max(hs + y1, 0), FH);
    he = min(max(he + y1, 0), FH);
    const int nh = he - hs;

    int nw[PPW];
    int off0[PPW], offL[PPW];   // first/last column offset (in float2 units), clamped safe
    int maxnw = 0;
    #pragma unroll
    for (int p = 0; p < PPW; ++p) {
        int a = (int)floorf(__fmul_rn((float)p, bw));
        int b = (int)ceilf(__fmul_rn((float)(p + 1), bw));
        int wsp = min(max(a + x1, 0), FW);
        int wep = min(max(b + x1, 0), FW);
        nw[p] = wep - wsp;
        maxnw = max(maxnw, nw[p]);
        int s = min(wsp, FW - 1);               // clamp into valid columns
        int l = min(max(wep - 1, s), FW - 1);
        off0[p] = s * NCG;
        offL[p] = l * NCG;
    }

    const float NEG_INF = __int_as_float(0xff800000);
    float2 m[PPW];
    #pragma unroll
    for (int p = 0; p < PPW; ++p) { m[p].x = NEG_INF; m[p].y = NEG_INF; }

    const float2* base = (const float2*)g_ft + cg;

    if (nh > 0 && maxnw > 0) {
        for (int h = hs; h < he; ++h) {
            const float2* row = base + h * (FW * NCG);
            int joff = 0;
            for (int j = 0; j < maxnw; ++j, joff += NCG) {
                float2 v[PPW];
                #pragma unroll
                for (int p = 0; p < PPW; ++p) {
                    v[p] = row[min(off0[p] + joff, offL[p])];   // 7 independent LDGs
                }
                #pragma unroll
                for (int p = 0; p < PPW; ++p) {
                    m[p].x = fmaxf(m[p].x, v[p].x);
                    m[p].y = fmaxf(m[p].y, v[p].y);
                }
            }
        }
    }

    #pragma unroll
    for (int p = 0; p < PPW; ++p) {
        float2 acc = m[p];
        if (nh <= 0 || nw[p] <= 0) { acc.x = 0.0f; acc.y = 0.0f; }  // empty bin -> 0
        s_out[(2 * cg + 0) * PPW + p] = acc.x;
        s_out[(2 * cg + 1) * PPW + p] = acc.y;
    }

    __syncthreads();

    // Coalesced write: out[roi][ch][ph*7 + pw]
    const int out_base = roi * OUT_PER_ROI + ph * PPW;
    #pragma unroll
    for (int k = 0; k < 2 * PPW; ++k) {     // 14 iterations of 128 threads
        int i  = k * NCG + cg;
        int ch = i / PPW;
        int pw = i - ch * PPW;
        out[out_base + ch * NBINS + pw] = s_out[i];
    }
}

extern "C" void kernel_launch(void* const* d_in, const int* in_sizes, int n_in,
                              void* d_out, int out_size) {
    const float* features = (const float*)d_in[0];
    const float* rois     = (const float*)d_in[1];
    const float* sscale   = (const float*)d_in[2];
    float* out = (float*)d_out;

    const int n_rois = in_sizes[1] / 5;

    dim3 tgrid((NHW + 31) / 32, NC / 32);
    transpose_kernel<<<tgrid, dim3(32, 32)>>>(features);

    pool_kernel<<<dim3(n_rois, PPH), NCG>>>(rois, sscale, out);
}

// round 14
// speedup vs baseline: 1.2398x; 1.2398x over previous
#include <cuda_runtime.h>

#define NC 256
#define NCG4 (NC / 4)       // 64 float4 channel-groups
#define FH 38
#define FW 38
#define NHW (FH * FW)       // 1444
#define PPH 7
#define PPW 7
#define NBINS (PPH * PPW)   // 49
#define OUT_PER_ROI (NC * NBINS)  // 12544

// Transposed features: [H][W][C], channel-contiguous for coalesced warp reads.
__device__ float g_ft[NHW * NC];

__global__ void transpose_kernel(const float* __restrict__ f) {
    __shared__ float t[32][33];
    const int hw0 = blockIdx.x * 32;
    const int c0  = blockIdx.y * 32;

    int hw = hw0 + threadIdx.x;
    int c  = c0 + threadIdx.y;
    if (hw < NHW) t[threadIdx.y][threadIdx.x] = f[c * NHW + hw];
    __syncthreads();

    int hw2 = hw0 + threadIdx.y;
    int c2  = c0 + threadIdx.x;
    if (hw2 < NHW) g_ft[hw2 * NC + c2] = t[threadIdx.x][threadIdx.y];
}

// Block = (roi, ph). 128 threads = 64 float4 channel-groups x 2 h-halves.
// Each half scans its h-subrange for all 7 pw-bins (7 independent LDG.128
// per j step, bin-clamped indices, no membership predicates), then the two
// halves are max-combined through shared memory.
__global__ void pool_kernel(const float* __restrict__ rois,
                            const float* __restrict__ sscale,
                            float* __restrict__ out) {
    __shared__ float4 s_part[NCG4 * PPW];   // half-1 partials, 7168 B
    __shared__ float  s_out[NC * PPW];      // final [ch][pw] slice, 7168 B

    const int roi  = blockIdx.x;
    const int ph   = blockIdx.y;
    const int tid  = threadIdx.x;
    const int cg   = tid & (NCG4 - 1);      // channels 4cg .. 4cg+3
    const int half = tid >> 6;              // 0 or 1
    const float scale = *sscale;

    const float* r = rois + roi * 5;
    // jnp.round = half-to-even = rintf
    const int x1 = (int)rintf(__fmul_rn(r[1], scale));
    const int y1 = (int)rintf(__fmul_rn(r[2], scale));
    const int x2 = (int)rintf(__fmul_rn(r[3], scale));
    const int y2 = (int)rintf(__fmul_rn(r[4], scale));

    // Match XLA: w/7 lowered to w * RN(1/7)
    const float RCP7 = 1.0f / 7.0f;
    const float bw = __fmul_rn((float)max(x2 - x1 + 1, 1), RCP7);
    const float bh = __fmul_rn((float)max(y2 - y1 + 1, 1), RCP7);

    int hs = (int)floorf(__fmul_rn((float)ph, bh));
    int he = (int)ceilf(__fmul_rn((float)(ph + 1), bh));
    hs = min(max(hs + y1, 0), FH);
    he = min(max(he + y1, 0), FH);
    const int nh = he - hs;

    // This half's h-subrange
    const int hmid = hs + ((nh + 1) >> 1);
    const int h0 = half ? hmid : hs;
    const int h1 = half ? he   : hmid;

    int nw[PPW], off0[PPW], offL[PPW];
    int maxnw = 0;
    #pragma unroll
    for (int p = 0; p < PPW; ++p) {
        int a = (int)floorf(__fmul_rn((float)p, bw));
        int b = (int)ceilf(__fmul_rn((float)(p + 1), bw));
        int wsp = min(max(a + x1, 0), FW);
        int wep = min(max(b + x1, 0), FW);
        nw[p] = wep - wsp;
        maxnw = max(maxnw, nw[p]);
        int s = min(wsp, FW - 1);
        int l = min(max(wep - 1, s), FW - 1);
        off0[p] = s * NCG4;                 // offsets in float4 units
        offL[p] = l * NCG4;
    }

    const float NEG_INF = __int_as_float(0xff800000);
    float4 m[PPW];
    #pragma unroll
    for (int p = 0; p < PPW; ++p) { m[p].x = m[p].y = m[p].z = m[p].w = NEG_INF; }

    const float4* base = (const float4*)g_ft + cg;

    if (h1 > h0 && maxnw > 0) {
        for (int h = h0; h < h1; ++h) {
            const float4* row = base + h * (FW * NCG4);
            int joff = 0;
            for (int j = 0; j < maxnw; ++j, joff += NCG4) {
                float4 v[PPW];
                #pragma unroll
                for (int p = 0; p < PPW; ++p)
                    v[p] = row[min(off0[p] + joff, offL[p])];  // 7 independent LDG.128
                #pragma unroll
                for (int p = 0; p < PPW; ++p) {
                    m[p].x = fmaxf(m[p].x, v[p].x);
                    m[p].y = fmaxf(m[p].y, v[p].y);
                    m[p].z = fmaxf(m[p].z, v[p].z);
                    m[p].w = fmaxf(m[p].w, v[p].w);
                }
            }
        }
    }

    // Half 1 publishes partials
    if (half) {
        #pragma unroll
        for (int p = 0; p < PPW; ++p) s_part[cg * PPW + p] = m[p];
    }
    __syncthreads();

    // Half 0 combines and writes the [ch][pw] float slice
    if (!half) {
        #pragma unroll
        for (int p = 0; p < PPW; ++p) {
            float4 o = s_part[cg * PPW + p];
            float4 a = m[p];
            a.x = fmaxf(a.x, o.x); a.y = fmaxf(a.y, o.y);
            a.z = fmaxf(a.z, o.z); a.w = fmaxf(a.w, o.w);
            if (nh <= 0 || nw[p] <= 0) { a.x = a.y = a.z = a.w = 0.0f; }
            s_out[(4 * cg + 0) * PPW + p] = a.x;
            s_out[(4 * cg + 1) * PPW + p] = a.y;
            s_out[(4 * cg + 2) * PPW + p] = a.z;
            s_out[(4 * cg + 3) * PPW + p] = a.w;
        }
    }
    __syncthreads();

    // Coalesced write: out[roi][ch][ph*7 + pw], 1792 floats by 128 threads
    const int out_base = roi * OUT_PER_ROI + ph * PPW;
    #pragma unroll
    for (int k = 0; k < 14; ++k) {
        int i  = k * 128 + tid;
        int ch = i / PPW;
        int pw = i - ch * PPW;
        out[out_base + ch * NBINS + pw] = s_out[i];
    }
}

extern "C" void kernel_launch(void* const* d_in, const int* in_sizes, int n_in,
                              void* d_out, int out_size) {
    const float* features = (const float*)d_in[0];
    const float* rois     = (const float*)d_in[1];
    const float* sscale   = (const float*)d_in[2];
    float* out = (float*)d_out;

    const int n_rois = in_sizes[1] / 5;

    dim3 tgrid((NHW + 31) / 32, NC / 32);
    transpose_kernel<<<tgrid, dim3(32, 32)>>>(features);

    pool_kernel<<<dim3(n_rois, PPH), 128>>>(rois, sscale, out);
}

// round 16
// speedup vs baseline: 1.2789x; 1.0316x over previous
#include <cuda_runtime.h>

#define NC 256
#define NCG4 (NC / 4)       // 64 float4 channel-groups
#define FH 38
#define FW 38
#define NHW (FH * FW)       // 1444
#define PPH 7
#define PPW 7
#define NBINS (PPH * PPW)   // 49
#define OUT_PER_ROI (NC * NBINS)  // 12544

// Transposed features: [H][W][C], channel-contiguous for coalesced warp reads.
__device__ float g_ft[NHW * NC];

__global__ void transpose_kernel(const float* __restrict__ f) {
    __shared__ float t[32][33];
    const int hw0 = blockIdx.x * 32;
    const int c0  = blockIdx.y * 32;

    int hw = hw0 + threadIdx.x;
    int c  = c0 + threadIdx.y;
    if (hw < NHW) t[threadIdx.y][threadIdx.x] = f[c * NHW + hw];
    __syncthreads();

    int hw2 = hw0 + threadIdx.y;
    int c2  = c0 + threadIdx.x;
    if (hw2 < NHW) g_ft[hw2 * NC + c2] = t[threadIdx.x][threadIdx.y];
}

// Block = (roi, ph). 128 threads = 64 float4 channel-groups x 2 h-halves.
// All 7 pw-bins share the h-range: per (h, j) issue 7 independent bin-clamped
// LDG.128s, no membership predicates. __launch_bounds__(128, 8) caps regs at
// 64 so 8 CTAs/SM stay resident (occupancy was the R14 binder at 79 regs).
__global__ void __launch_bounds__(128, 8)
pool_kernel(const float* __restrict__ rois,
            const float* __restrict__ sscale,
            float* __restrict__ out) {
    __shared__ float4 s_part[NCG4 * PPW];   // half-1 partials
    __shared__ float  s_out[NC * PPW];      // final [ch][pw] slice

    const int roi  = blockIdx.x;
    const int ph   = blockIdx.y;
    const int tid  = threadIdx.x;
    const int cg   = tid & (NCG4 - 1);      // channels 4cg .. 4cg+3
    const int half = tid >> 6;              // 0 or 1
    const float scale = *sscale;

    const float* r = rois + roi * 5;
    // jnp.round = half-to-even = rintf
    const int x1 = (int)rintf(__fmul_rn(r[1], scale));
    const int y1 = (int)rintf(__fmul_rn(r[2], scale));
    const int x2 = (int)rintf(__fmul_rn(r[3], scale));
    const int y2 = (int)rintf(__fmul_rn(r[4], scale));

    // Match XLA: w/7 lowered to w * RN(1/7)
    const float RCP7 = 1.0f / 7.0f;
    const float bw = __fmul_rn((float)max(x2 - x1 + 1, 1), RCP7);
    const float bh = __fmul_rn((float)max(y2 - y1 + 1, 1), RCP7);

    int hs = (int)floorf(__fmul_rn((float)ph, bh));
    int he = (int)ceilf(__fmul_rn((float)(ph + 1), bh));
    hs = min(max(hs + y1, 0), FH);
    he = min(max(he + y1, 0), FH);
    const int nh = he - hs;

    // This half's h-subrange
    const int hmid = hs + ((nh + 1) >> 1);
    const int h0 = half ? hmid : hs;
    const int h1 = half ? he   : hmid;

    int off0[PPW], offL[PPW];
    unsigned empty_mask = (nh <= 0) ? 0x7F : 0;   // bit p: bin p -> 0
    int maxnw = 0;
    #pragma unroll
    for (int p = 0; p < PPW; ++p) {
        int a = (int)floorf(__fmul_rn((float)p, bw));
        int b = (int)ceilf(__fmul_rn((float)(p + 1), bw));
        int wsp = min(max(a + x1, 0), FW);
        int wep = min(max(b + x1, 0), FW);
        if (wep <= wsp) empty_mask |= 1u << p;
        maxnw = max(maxnw, wep - wsp);
        int s = min(wsp, FW - 1);
        int l = min(max(wep - 1, s), FW - 1);
        off0[p] = s * NCG4;                 // offsets in float4 units
        offL[p] = l * NCG4;
    }

    const float NEG_INF = __int_as_float(0xff800000);
    float4 m[PPW];
    #pragma unroll
    for (int p = 0; p < PPW; ++p) { m[p].x = m[p].y = m[p].z = m[p].w = NEG_INF; }

    const float4* base = (const float4*)g_ft + cg;

    if (h1 > h0 && maxnw > 0) {
        for (int h = h0; h < h1; ++h) {
            const float4* row = base + h * (FW * NCG4);
            int joff = 0;
            for (int j = 0; j < maxnw; ++j, joff += NCG4) {
                float4 v[PPW];
                #pragma unroll
                for (int p = 0; p < PPW; ++p)
                    v[p] = row[min(off0[p] + joff, offL[p])];  // independent LDG.128s
                #pragma unroll
                for (int p = 0; p < PPW; ++p) {
                    m[p].x = fmaxf(m[p].x, v[p].x);
                    m[p].y = fmaxf(m[p].y, v[p].y);
                    m[p].z = fmaxf(m[p].z, v[p].z);
                    m[p].w = fmaxf(m[p].w, v[p].w);
                }
            }
        }
    }

    // Half 1 publishes partials
    if (half) {
        #pragma unroll
        for (int p = 0; p < PPW; ++p) s_part[cg * PPW + p] = m[p];
    }
    __syncthreads();

    // Half 0 combines and writes the [ch][pw] float slice
    if (!half) {
        #pragma unroll
        for (int p = 0; p < PPW; ++p) {
            float4 o = s_part[cg * PPW + p];
            float4 a = m[p];
            a.x = fmaxf(a.x, o.x); a.y = fmaxf(a.y, o.y);
            a.z = fmaxf(a.z, o.z); a.w = fmaxf(a.w, o.w);
            if ((empty_mask >> p) & 1u) { a.x = a.y = a.z = a.w = 0.0f; }
            s_out[(4 * cg + 0) * PPW + p] = a.x;
            s_out[(4 * cg + 1) * PPW + p] = a.y;
            s_out[(4 * cg + 2) * PPW + p] = a.z;
            s_out[(4 * cg + 3) * PPW + p] = a.w;
        }
    }
    __syncthreads();

    // Coalesced write: out[roi][ch][ph*7 + pw], 1792 floats by 128 threads
    const int out_base = roi * OUT_PER_ROI + ph * PPW;
    #pragma unroll
    for (int k = 0; k < 14; ++k) {
        int i  = k * 128 + tid;
        int ch = i / PPW;
        int pw = i - ch * PPW;
        out[out_base + ch * NBINS + pw] = s_out[i];
    }
}

extern "C" void kernel_launch(void* const* d_in, const int* in_sizes, int n_in,
                              void* d_out, int out_size) {
    const float* features = (const float*)d_in[0];
    const float* rois     = (const float*)d_in[1];
    const float* sscale   = (const float*)d_in[2];
    float* out = (float*)d_out;

    const int n_rois = in_sizes[1] / 5;

    dim3 tgrid((NHW + 31) / 32, NC / 32);
    transpose_kernel<<<tgrid, dim3(32, 32)>>>(features);

    pool_kernel<<<dim3(n_rois, PPH), 128>>>(rois, sscale, out);
}

// round 17
// speedup vs baseline: 1.3370x; 1.0454x over previous
#include <cuda_runtime.h>

#define NC 256
#define NCG4 (NC / 4)       // 64 float4 channel-groups
#define FH 38
#define FW 38
#define NHW (FH * FW)       // 1444
#define PPH 7
#define PPW 7
#define NBINS (PPH * PPW)   // 49
#define OUT_PER_ROI (NC * NBINS)  // 12544

// Transposed features: [H][W][C], channel-contiguous for coalesced warp reads.
__device__ float g_ft[NHW * NC];

__global__ void transpose_kernel(const float* __restrict__ f) {
    __shared__ float t[32][33];
    const int hw0 = blockIdx.x * 32;
    const int c0  = blockIdx.y * 32;

    int hw = hw0 + threadIdx.x;
    int c  = c0 + threadIdx.y;
    if (hw < NHW) t[threadIdx.y][threadIdx.x] = f[c * NHW + hw];
    __syncthreads();

    int hw2 = hw0 + threadIdx.y;
    int c2  = c0 + threadIdx.x;
    if (hw2 < NHW) g_ft[hw2 * NC + c2] = t[threadIdx.x][threadIdx.y];
}

// Block = (roi, ph). 256 threads = 64 float4 channel-groups x 4 work-quarters.
// The (h, j) scan space (total = nh*maxnw) is linearized and split EVENLY
// across the 4 quarters -- no idle halves when nh==1 (the R16 occupancy bug).
// Per step: 7 independent bin-clamped LDG.128s, no membership predicates.
__global__ void __launch_bounds__(256, 4)
pool_kernel(const float* __restrict__ rois,
            const float* __restrict__ sscale,
            float* __restrict__ out) {
    __shared__ float4 s_part[4 * NCG4 * PPW];  // [q][cg][p], 28672 B
    __shared__ float  s_out[NC * PPW];         // final [ch][pw] slice, 7168 B

    const int roi = blockIdx.x;
    const int ph  = blockIdx.y;
    const int tid = threadIdx.x;
    const int cg  = tid & (NCG4 - 1);          // channels 4cg .. 4cg+3
    const int q   = tid >> 6;                  // work-quarter 0..3
    const float scale = *sscale;

    const float* r = rois + roi * 5;
    // jnp.round = half-to-even = rintf
    const int x1 = (int)rintf(__fmul_rn(r[1], scale));
    const int y1 = (int)rintf(__fmul_rn(r[2], scale));
    const int x2 = (int)rintf(__fmul_rn(r[3], scale));
    const int y2 = (int)rintf(__fmul_rn(r[4], scale));

    // Match XLA: w/7 lowered to w * RN(1/7)
    const float RCP7 = 1.0f / 7.0f;
    const float bw = __fmul_rn((float)max(x2 - x1 + 1, 1), RCP7);
    const float bh = __fmul_rn((float)max(y2 - y1 + 1, 1), RCP7);

    int hs = (int)floorf(__fmul_rn((float)ph, bh));
    int he = (int)ceilf(__fmul_rn((float)(ph + 1), bh));
    hs = min(max(hs + y1, 0), FH);
    he = min(max(he + y1, 0), FH);
    const int nh = he - hs;

    int off0[PPW], offL[PPW];
    unsigned empty_mask = (nh <= 0) ? 0x7F : 0;
    int maxnw = 0;
    #pragma unroll
    for (int p = 0; p < PPW; ++p) {
        int a = (int)floorf(__fmul_rn((float)p, bw));
        int b = (int)ceilf(__fmul_rn((float)(p + 1), bw));
        int wsp = min(max(a + x1, 0), FW);
        int wep = min(max(b + x1, 0), FW);
        if (wep <= wsp) empty_mask |= 1u << p;
        maxnw = max(maxnw, wep - wsp);
        int s = min(wsp, FW - 1);
        int l = min(max(wep - 1, s), FW - 1);
        off0[p] = s * NCG4;                    // offsets in float4 units
        offL[p] = l * NCG4;
    }

    const float NEG_INF = __int_as_float(0xff800000);
    float4 m[PPW];
    #pragma unroll
    for (int p = 0; p < PPW; ++p) { m[p].x = m[p].y = m[p].z = m[p].w = NEG_INF; }

    const float4* base = (const float4*)g_ft + cg;

    const int total = (nh > 0) ? nh * maxnw : 0;
    if (total > 0) {
        const int per = (total + 3) >> 2;
        const int i0  = q * per;
        const int i1  = min(total, i0 + per);
        if (i0 < i1) {
            int h = hs + i0 / maxnw;           // one div to seed
            int j = i0 - (h - hs) * maxnw;
            const float4* row = base + h * (FW * NCG4);
            int joff = j * NCG4;
            for (int i = i0; i < i1; ++i) {
                float4 v[PPW];
                #pragma unroll
                for (int p = 0; p < PPW; ++p)
                    v[p] = row[min(off0[p] + joff, offL[p])];  // 7 indep LDG.128
                #pragma unroll
                for (int p = 0; p < PPW; ++p) {
                    m[p].x = fmaxf(m[p].x, v[p].x);
                    m[p].y = fmaxf(m[p].y, v[p].y);
                    m[p].z = fmaxf(m[p].z, v[p].z);
                    m[p].w = fmaxf(m[p].w, v[p].w);
                }
                if (++j == maxnw) { j = 0; joff = 0; row += FW * NCG4; }
                else joff += NCG4;
            }
        }
    }

    // Publish partials
    #pragma unroll
    for (int p = 0; p < PPW; ++p) s_part[(q * NCG4 + cg) * PPW + p] = m[p];
    __syncthreads();

    // First quarter combines 4 partials and writes the [ch][pw] slice
    if (q == 0) {
        #pragma unroll
        for (int p = 0; p < PPW; ++p) {
            float4 a = s_part[(0 * NCG4 + cg) * PPW + p];
            #pragma unroll
            for (int qq = 1; qq < 4; ++qq) {
                float4 o = s_part[(qq * NCG4 + cg) * PPW + p];
                a.x = fmaxf(a.x, o.x); a.y = fmaxf(a.y, o.y);
                a.z = fmaxf(a.z, o.z); a.w = fmaxf(a.w, o.w);
            }
            if ((empty_mask >> p) & 1u) { a.x = a.y = a.z = a.w = 0.0f; }
            s_out[(4 * cg + 0) * PPW + p] = a.x;
            s_out[(4 * cg + 1) * PPW + p] = a.y;
            s_out[(4 * cg + 2) * PPW + p] = a.z;
            s_out[(4 * cg + 3) * PPW + p] = a.w;
        }
    }
    __syncthreads();

    // Coalesced write: out[roi][ch][ph*7 + pw], 1792 floats by 256 threads
    const int out_base = roi * OUT_PER_ROI + ph * PPW;
    #pragma unroll
    for (int k = 0; k < 7; ++k) {
        int i  = k * 256 + tid;
        int ch = i / PPW;
        int pw = i - ch * PPW;
        out[out_base + ch * NBINS + pw] = s_out[i];
    }
}

extern "C" void kernel_launch(void* const* d_in, const int* in_sizes, int n_in,
                              void* d_out, int out_size) {
    const float* features = (const float*)d_in[0];
    const float* rois     = (const float*)d_in[1];
    const float* sscale   = (const float*)d_in[2];
    float* out = (float*)d_out;

    const int n_rois = in_sizes[1] / 5;

    dim3 tgrid((NHW + 31) / 32, NC / 32);
    transpose_kernel<<<tgrid, dim3(32, 32)>>>(features);

    pool_kernel<<<dim3(n_rois, PPH), 256>>>(rois, sscale, out);
}